// round 10
// baseline (speedup 1.0000x reference)
#include <cuda_runtime.h>

// BilateralBlur: barrier-free streaming separable depth-guided blur, 2 px/thread.
// B=8, H=1024, W=1024, R=2 (K=5). Block = 128 threads x 2 px = 256 columns.
// Rows stream through 5-deep float2 register rings; chunk of 5 keeps slots static.
// Exact R4 structure (best codegen: straight-line unrolled body, batched loads);
// only change: launch_bounds occupancy 5 -> 6 to grow the resident warp pool.

#define HDIM 1024
#define WDIM 1024
#define BATCH 8
#define NT 128
#define PX 2
#define TILEW (NT * PX)     // 256
#define HSTRIP 32
#define NCHUNK 8            // 40 stream rows, emissions at m=4..35

__device__ __forceinline__ float f_ex2(float x){ float y; asm("ex2.approx.ftz.f32 %0, %1;" : "=f"(y) : "f"(x)); return y; }
__device__ __forceinline__ float f_lg2(float x){ float y; asm("lg2.approx.ftz.f32 %0, %1;" : "=f"(y) : "f"(x)); return y; }
__device__ __forceinline__ float f_rcp(float x){ float y; asm("rcp.approx.ftz.f32 %0, %1;" : "=f"(y) : "f"(x)); return y; }

__global__ __launch_bounds__(NT, 6)
void bilat_px2o_kernel(const float* __restrict__ bright,
                       const float* __restrict__ dark,
                       const float* __restrict__ depths,
                       const float* __restrict__ s_dv,
                       const float* __restrict__ s_sv,
                       const float* __restrict__ s_de,
                       const float* __restrict__ s_eps,
                       const float* __restrict__ s_ce,
                       float* __restrict__ out)
{
    const float L2E = 1.4426950408889634f;
    const float dv  = __ldg(s_dv);
    const float sv  = __ldg(s_sv);
    const float de  = __ldg(s_de);
    const float eps = __ldg(s_eps);
    const float ce  = __ldg(s_ce);
    const float c1  = -L2E / (2.0f * dv);   // depth-weight exponent coeff (log2)
    const float q1  = -L2E / (2.0f * sv);   // spatial log2-weight, |offset|=1
    const float q4  = 4.0f * q1;            // |offset|=2

    const int tid  = threadIdx.x;
    const int col0 = blockIdx.x * TILEW + tid * PX;  // even, always valid
    const int y0   = blockIdx.y * HSTRIP;
    const int base = blockIdx.z * (HDIM * WDIM);

    const bool lv = (col0 != 0);             // left halo (cols col0-2,col0-1) valid
    const bool rv = (col0 + PX < WDIM);      // right halo (cols col0+2,col0+3) valid
    const int offL = lv ? -2 : 0;            // clamped float offsets if OOB
    const int offR = rv ?  2 : 0;

    float2 rz[5], rbx[5], rdx[5];            // stream row m -> slot m%5

    #pragma unroll 1
    for (int c = 0; c < NCHUNK; c++) {
        #pragma unroll
        for (int rr = 0; rr < 5; rr++) {
            const int m  = c * 5 + rr;
            const int gy = y0 - 2 + m;
            const bool rowv = ((unsigned)gy) < (unsigned)HDIM;
            const int gyc = rowv ? gy : (gy < 0 ? 0 : HDIM - 1);
            const int ro  = base + gyc * WDIM + col0;

            const float* pz = depths + ro;
            const float* pb = bright + ro;
            const float* pd = dark   + ro;
            const float2 zL = __ldg((const float2*)(pz + offL));
            const float2 zC = __ldg((const float2*)pz);
            const float2 zR = __ldg((const float2*)(pz + offR));
            const float2 bL = __ldg((const float2*)(pb + offL));
            const float2 bC = __ldg((const float2*)pb);
            const float2 bR = __ldg((const float2*)(pb + offR));
            const float2 dL = __ldg((const float2*)(pd + offL));
            const float2 dC = __ldg((const float2*)pd);
            const float2 dR = __ldg((const float2*)(pd + offR));

            // invalid tap => z forced to 0 => rel=1 => weight underflows to exactly 0
            const bool lm = rowv & lv;
            const bool rm = rowv & rv;
            float z6[6], b6[6], d6[6];
            z6[0] = lm   ? zL.x : 0.f;  z6[1] = lm   ? zL.y : 0.f;
            z6[2] = rowv ? zC.x : 0.f;  z6[3] = rowv ? zC.y : 0.f;
            z6[4] = rm   ? zR.x : 0.f;  z6[5] = rm   ? zR.y : 0.f;
            b6[0] = bL.x; b6[1] = bL.y; b6[2] = bC.x; b6[3] = bC.y; b6[4] = bR.x; b6[5] = bR.y;
            d6[0] = dL.x; d6[1] = dL.y; d6[2] = dC.x; d6[3] = dC.y; d6[4] = dR.x; d6[5] = dR.y;

            // ---- horizontal blur (center tap weight = 1, skipped)
            float bx[PX], dx[PX];
            #pragma unroll
            for (int p = 0; p < PX; p++) {
                const float iz = f_rcp(z6[2 + p]);
                float ws = 1.f, bs = b6[2 + p], ds = d6[2 + p];
                #pragma unroll
                for (int k = 0; k < 5; k++) {
                    if (k == 2) continue;
                    const float sw = (k == 0 || k == 4) ? q4 : q1;
                    float rel = fminf(fabsf(fmaf(z6[p + k], iz, -1.f)), 1.f);
                    float w = f_ex2(fmaf(rel * rel, c1, sw));
                    ws += w;
                    bs = fmaf(w, b6[p + k], bs);
                    ds = fmaf(w, d6[p + k], ds);
                }
                const float r = f_rcp(ws);
                bx[p] = rowv ? bs * r : 0.f;   // keep NaN out for pad rows
                dx[p] = rowv ? ds * r : 0.f;
            }
            rz[rr]  = make_float2(z6[2], z6[3]);   // 0 for pad rows
            rbx[rr] = make_float2(bx[0], bx[1]);
            rdx[rr] = make_float2(dx[0], dx[1]);

            // ---- vertical blur + blend, output image row y0 + m - 4
            if (m >= 4 && m < HSTRIP + 4) {
                const int sc = (rr + 3) % 5;       // center slot (stream row m-2)
                const int ooff = base + (y0 + m - 4) * WDIM + col0;
                const float2 bCe = __ldg((const float2*)(bright + ooff));
                const float2 dCe = __ldg((const float2*)(dark   + ooff));
                float res[PX];
                #pragma unroll
                for (int p = 0; p < PX; p++) {
                    const float izc = f_rcp(p ? rz[sc].y : rz[sc].x);
                    float vws = 1.f;
                    float vbs = p ? rbx[sc].y : rbx[sc].x;
                    float vds = p ? rdx[sc].y : rdx[sc].x;
                    #pragma unroll
                    for (int j = 0; j < 5; j++) {
                        if (j == 2) continue;
                        const int sj = (rr + 1 + j) % 5;   // tap stream row m-4+j
                        const float sw = (j == 0 || j == 4) ? q4 : q1;
                        const float zj = p ? rz[sj].y : rz[sj].x;
                        float rel = fminf(fabsf(fmaf(zj, izc, -1.f)), 1.f);
                        float w = f_ex2(fmaf(rel * rel, c1, sw));
                        vws += w;
                        vbs = fmaf(w, p ? rbx[sj].y : rbx[sj].x, vbs);
                        vds = fmaf(w, p ? rdx[sj].y : rdx[sj].x, vds);
                    }
                    const float vr = f_rcp(vws);
                    const float bm = vbs * vr, dm = vds * vr;
                    const float b = p ? bCe.y : bCe.x;
                    const float d = p ? dCe.y : dCe.x;

                    // custom_pow(a, de) = exp2(de * log2(max(a, 1e-8)))
                    float devb = f_ex2(de * f_lg2(fmaxf(fabsf(b - bm), 1e-8f))) * ce;
                    float devd = fmaxf(f_ex2(de * f_lg2(fmaxf(fabsf(d - dm), 1e-8f))), eps);
                    float s = f_rcp(devb + devd);
                    res[p] = (devd * b + devb * d) * s;
                }
                *reinterpret_cast<float2*>(out + ooff) = make_float2(res[0], res[1]);
            }
        }
    }
}

extern "C" void kernel_launch(void* const* d_in, const int* in_sizes, int n_in,
                              void* d_out, int out_size)
{
    const float* bright = (const float*)d_in[0];
    const float* dark   = (const float*)d_in[1];
    const float* depths = (const float*)d_in[2];
    const float* dv     = (const float*)d_in[3];
    const float* sv     = (const float*)d_in[4];
    const float* de     = (const float*)d_in[5];
    const float* eps    = (const float*)d_in[6];
    const float* ce     = (const float*)d_in[7];
    float* out = (float*)d_out;

    dim3 grid(WDIM / TILEW, HDIM / HSTRIP, BATCH);
    bilat_px2o_kernel<<<grid, NT>>>(bright, dark, depths, dv, sv, de, eps, ce, out);
}

// round 12
// speedup vs baseline: 1.4345x; 1.4345x over previous
#include <cuda_runtime.h>

// BilateralBlur: barrier-free streaming separable depth-guided blur, 2 px/thread.
// B=8, H=1024, W=1024, R=2 (K=5). Block = 128 threads x 2 px = 256 columns.
// R4 body EXACTLY (best per-warp codegen); strip halved to 16 rows so the grid
// is 2048 blocks -> 3 waves at occ 5 (tail overhead 1.08x instead of 1.45x).
// Horizontal overhead unchanged: 20 streamed rows / 16 emitted = 1.25 (= 40/32).

#define HDIM 1024
#define WDIM 1024
#define BATCH 8
#define NT 128
#define PX 2
#define TILEW (NT * PX)     // 256
#define HSTRIP 16
#define NCHUNK 4            // 20 stream rows, emissions at m=4..19

__device__ __forceinline__ float f_ex2(float x){ float y; asm("ex2.approx.ftz.f32 %0, %1;" : "=f"(y) : "f"(x)); return y; }
__device__ __forceinline__ float f_lg2(float x){ float y; asm("lg2.approx.ftz.f32 %0, %1;" : "=f"(y) : "f"(x)); return y; }
__device__ __forceinline__ float f_rcp(float x){ float y; asm("rcp.approx.ftz.f32 %0, %1;" : "=f"(y) : "f"(x)); return y; }

__global__ __launch_bounds__(NT, 5)
void bilat_px2w_kernel(const float* __restrict__ bright,
                       const float* __restrict__ dark,
                       const float* __restrict__ depths,
                       const float* __restrict__ s_dv,
                       const float* __restrict__ s_sv,
                       const float* __restrict__ s_de,
                       const float* __restrict__ s_eps,
                       const float* __restrict__ s_ce,
                       float* __restrict__ out)
{
    const float L2E = 1.4426950408889634f;
    const float dv  = __ldg(s_dv);
    const float sv  = __ldg(s_sv);
    const float de  = __ldg(s_de);
    const float eps = __ldg(s_eps);
    const float ce  = __ldg(s_ce);
    const float c1  = -L2E / (2.0f * dv);   // depth-weight exponent coeff (log2)
    const float q1  = -L2E / (2.0f * sv);   // spatial log2-weight, |offset|=1
    const float q4  = 4.0f * q1;            // |offset|=2

    const int tid  = threadIdx.x;
    const int col0 = blockIdx.x * TILEW + tid * PX;  // even, always valid
    const int y0   = blockIdx.y * HSTRIP;
    const int base = blockIdx.z * (HDIM * WDIM);

    const bool lv = (col0 != 0);             // left halo (cols col0-2,col0-1) valid
    const bool rv = (col0 + PX < WDIM);      // right halo (cols col0+2,col0+3) valid
    const int offL = lv ? -2 : 0;            // clamped float offsets if OOB
    const int offR = rv ?  2 : 0;

    float2 rz[5], rbx[5], rdx[5];            // stream row m -> slot m%5

    #pragma unroll 1
    for (int c = 0; c < NCHUNK; c++) {
        #pragma unroll
        for (int rr = 0; rr < 5; rr++) {
            const int m  = c * 5 + rr;
            const int gy = y0 - 2 + m;
            const bool rowv = ((unsigned)gy) < (unsigned)HDIM;
            const int gyc = rowv ? gy : (gy < 0 ? 0 : HDIM - 1);
            const int ro  = base + gyc * WDIM + col0;

            const float* pz = depths + ro;
            const float* pb = bright + ro;
            const float* pd = dark   + ro;
            const float2 zL = __ldg((const float2*)(pz + offL));
            const float2 zC = __ldg((const float2*)pz);
            const float2 zR = __ldg((const float2*)(pz + offR));
            const float2 bL = __ldg((const float2*)(pb + offL));
            const float2 bC = __ldg((const float2*)pb);
            const float2 bR = __ldg((const float2*)(pb + offR));
            const float2 dL = __ldg((const float2*)(pd + offL));
            const float2 dC = __ldg((const float2*)pd);
            const float2 dR = __ldg((const float2*)(pd + offR));

            // invalid tap => z forced to 0 => rel=1 => weight underflows to exactly 0
            const bool lm = rowv & lv;
            const bool rm = rowv & rv;
            float z6[6], b6[6], d6[6];
            z6[0] = lm   ? zL.x : 0.f;  z6[1] = lm   ? zL.y : 0.f;
            z6[2] = rowv ? zC.x : 0.f;  z6[3] = rowv ? zC.y : 0.f;
            z6[4] = rm   ? zR.x : 0.f;  z6[5] = rm   ? zR.y : 0.f;
            b6[0] = bL.x; b6[1] = bL.y; b6[2] = bC.x; b6[3] = bC.y; b6[4] = bR.x; b6[5] = bR.y;
            d6[0] = dL.x; d6[1] = dL.y; d6[2] = dC.x; d6[3] = dC.y; d6[4] = dR.x; d6[5] = dR.y;

            // ---- horizontal blur (center tap weight = 1, skipped)
            float bx[PX], dx[PX];
            #pragma unroll
            for (int p = 0; p < PX; p++) {
                const float iz = f_rcp(z6[2 + p]);
                float ws = 1.f, bs = b6[2 + p], ds = d6[2 + p];
                #pragma unroll
                for (int k = 0; k < 5; k++) {
                    if (k == 2) continue;
                    const float sw = (k == 0 || k == 4) ? q4 : q1;
                    float rel = fminf(fabsf(fmaf(z6[p + k], iz, -1.f)), 1.f);
                    float w = f_ex2(fmaf(rel * rel, c1, sw));
                    ws += w;
                    bs = fmaf(w, b6[p + k], bs);
                    ds = fmaf(w, d6[p + k], ds);
                }
                const float r = f_rcp(ws);
                bx[p] = rowv ? bs * r : 0.f;   // keep NaN out for pad rows
                dx[p] = rowv ? ds * r : 0.f;
            }
            rz[rr]  = make_float2(z6[2], z6[3]);   // 0 for pad rows
            rbx[rr] = make_float2(bx[0], bx[1]);
            rdx[rr] = make_float2(dx[0], dx[1]);

            // ---- vertical blur + blend, output image row y0 + m - 4
            if (m >= 4 && m < HSTRIP + 4) {
                const int sc = (rr + 3) % 5;       // center slot (stream row m-2)
                const int ooff = base + (y0 + m - 4) * WDIM + col0;
                const float2 bCe = __ldg((const float2*)(bright + ooff));
                const float2 dCe = __ldg((const float2*)(dark   + ooff));
                float res[PX];
                #pragma unroll
                for (int p = 0; p < PX; p++) {
                    const float izc = f_rcp(p ? rz[sc].y : rz[sc].x);
                    float vws = 1.f;
                    float vbs = p ? rbx[sc].y : rbx[sc].x;
                    float vds = p ? rdx[sc].y : rdx[sc].x;
                    #pragma unroll
                    for (int j = 0; j < 5; j++) {
                        if (j == 2) continue;
                        const int sj = (rr + 1 + j) % 5;   // tap stream row m-4+j
                        const float sw = (j == 0 || j == 4) ? q4 : q1;
                        const float zj = p ? rz[sj].y : rz[sj].x;
                        float rel = fminf(fabsf(fmaf(zj, izc, -1.f)), 1.f);
                        float w = f_ex2(fmaf(rel * rel, c1, sw));
                        vws += w;
                        vbs = fmaf(w, p ? rbx[sj].y : rbx[sj].x, vbs);
                        vds = fmaf(w, p ? rdx[sj].y : rdx[sj].x, vds);
                    }
                    const float vr = f_rcp(vws);
                    const float bm = vbs * vr, dm = vds * vr;
                    const float b = p ? bCe.y : bCe.x;
                    const float d = p ? dCe.y : dCe.x;

                    // custom_pow(a, de) = exp2(de * log2(max(a, 1e-8)))
                    float devb = f_ex2(de * f_lg2(fmaxf(fabsf(b - bm), 1e-8f))) * ce;
                    float devd = fmaxf(f_ex2(de * f_lg2(fmaxf(fabsf(d - dm), 1e-8f))), eps);
                    float s = f_rcp(devb + devd);
                    res[p] = (devd * b + devb * d) * s;
                }
                *reinterpret_cast<float2*>(out + ooff) = make_float2(res[0], res[1]);
            }
        }
    }
}

extern "C" void kernel_launch(void* const* d_in, const int* in_sizes, int n_in,
                              void* d_out, int out_size)
{
    const float* bright = (const float*)d_in[0];
    const float* dark   = (const float*)d_in[1];
    const float* depths = (const float*)d_in[2];
    const float* dv     = (const float*)d_in[3];
    const float* sv     = (const float*)d_in[4];
    const float* de     = (const float*)d_in[5];
    const float* eps    = (const float*)d_in[6];
    const float* ce     = (const float*)d_in[7];
    float* out = (float*)d_out;

    dim3 grid(WDIM / TILEW, HDIM / HSTRIP, BATCH);
    bilat_px2w_kernel<<<grid, NT>>>(bright, dark, depths, dv, sv, de, eps, ce, out);
}

// round 13
// speedup vs baseline: 1.4729x; 1.0268x over previous
#include <cuda_runtime.h>

// BilateralBlur: barrier-free streaming separable depth-guided blur, 2 px/thread.
// B=8, H=1024, W=1024, R=2 (K=5). Block = 128 threads x 2 px = 256 columns.
// R4/R12 body EXACTLY. Decomposition: 4 x-tiles x 23 y-strips x 8 batches =
// 736 blocks = ONE wave at occ 5 (n_conc=740): zero tail quantization.
// HSTRIP=46 -> 50 streamed rows = 10 full chunks (no break); halo overhead 1.087.
// Bottom strip clamps y0; overlapped rows are rewritten with identical values.

#define HDIM 1024
#define WDIM 1024
#define BATCH 8
#define NT 128
#define PX 2
#define TILEW (NT * PX)     // 256
#define HSTRIP 46
#define YBLOCKS 23          // ceil(1024/46)
#define NCHUNK 10           // 50 stream rows, emissions at m=4..49

__device__ __forceinline__ float f_ex2(float x){ float y; asm("ex2.approx.ftz.f32 %0, %1;" : "=f"(y) : "f"(x)); return y; }
__device__ __forceinline__ float f_lg2(float x){ float y; asm("lg2.approx.ftz.f32 %0, %1;" : "=f"(y) : "f"(x)); return y; }
__device__ __forceinline__ float f_rcp(float x){ float y; asm("rcp.approx.ftz.f32 %0, %1;" : "=f"(y) : "f"(x)); return y; }

__global__ __launch_bounds__(NT, 5)
void bilat_px2p_kernel(const float* __restrict__ bright,
                       const float* __restrict__ dark,
                       const float* __restrict__ depths,
                       const float* __restrict__ s_dv,
                       const float* __restrict__ s_sv,
                       const float* __restrict__ s_de,
                       const float* __restrict__ s_eps,
                       const float* __restrict__ s_ce,
                       float* __restrict__ out)
{
    const float L2E = 1.4426950408889634f;
    const float dv  = __ldg(s_dv);
    const float sv  = __ldg(s_sv);
    const float de  = __ldg(s_de);
    const float eps = __ldg(s_eps);
    const float ce  = __ldg(s_ce);
    const float c1  = -L2E / (2.0f * dv);   // depth-weight exponent coeff (log2)
    const float q1  = -L2E / (2.0f * sv);   // spatial log2-weight, |offset|=1
    const float q4  = 4.0f * q1;            // |offset|=2

    const int tid  = threadIdx.x;
    const int col0 = blockIdx.x * TILEW + tid * PX;  // even, always valid
    int y0 = blockIdx.y * HSTRIP;
    if (y0 > HDIM - HSTRIP) y0 = HDIM - HSTRIP;      // bottom strip overlaps (same values)
    const int base = blockIdx.z * (HDIM * WDIM);

    const bool lv = (col0 != 0);             // left halo (cols col0-2,col0-1) valid
    const bool rv = (col0 + PX < WDIM);      // right halo (cols col0+2,col0+3) valid
    const int offL = lv ? -2 : 0;            // clamped float offsets if OOB
    const int offR = rv ?  2 : 0;

    float2 rz[5], rbx[5], rdx[5];            // stream row m -> slot m%5

    #pragma unroll 1
    for (int c = 0; c < NCHUNK; c++) {
        #pragma unroll
        for (int rr = 0; rr < 5; rr++) {
            const int m  = c * 5 + rr;
            const int gy = y0 - 2 + m;
            const bool rowv = ((unsigned)gy) < (unsigned)HDIM;
            const int gyc = rowv ? gy : (gy < 0 ? 0 : HDIM - 1);
            const int ro  = base + gyc * WDIM + col0;

            const float* pz = depths + ro;
            const float* pb = bright + ro;
            const float* pd = dark   + ro;
            const float2 zL = __ldg((const float2*)(pz + offL));
            const float2 zC = __ldg((const float2*)pz);
            const float2 zR = __ldg((const float2*)(pz + offR));
            const float2 bL = __ldg((const float2*)(pb + offL));
            const float2 bC = __ldg((const float2*)pb);
            const float2 bR = __ldg((const float2*)(pb + offR));
            const float2 dL = __ldg((const float2*)(pd + offL));
            const float2 dC = __ldg((const float2*)pd);
            const float2 dR = __ldg((const float2*)(pd + offR));

            // invalid tap => z forced to 0 => rel=1 => weight underflows to exactly 0
            const bool lm = rowv & lv;
            const bool rm = rowv & rv;
            float z6[6], b6[6], d6[6];
            z6[0] = lm   ? zL.x : 0.f;  z6[1] = lm   ? zL.y : 0.f;
            z6[2] = rowv ? zC.x : 0.f;  z6[3] = rowv ? zC.y : 0.f;
            z6[4] = rm   ? zR.x : 0.f;  z6[5] = rm   ? zR.y : 0.f;
            b6[0] = bL.x; b6[1] = bL.y; b6[2] = bC.x; b6[3] = bC.y; b6[4] = bR.x; b6[5] = bR.y;
            d6[0] = dL.x; d6[1] = dL.y; d6[2] = dC.x; d6[3] = dC.y; d6[4] = dR.x; d6[5] = dR.y;

            // ---- horizontal blur (center tap weight = 1, skipped)
            float bx[PX], dx[PX];
            #pragma unroll
            for (int p = 0; p < PX; p++) {
                const float iz = f_rcp(z6[2 + p]);
                float ws = 1.f, bs = b6[2 + p], ds = d6[2 + p];
                #pragma unroll
                for (int k = 0; k < 5; k++) {
                    if (k == 2) continue;
                    const float sw = (k == 0 || k == 4) ? q4 : q1;
                    float rel = fminf(fabsf(fmaf(z6[p + k], iz, -1.f)), 1.f);
                    float w = f_ex2(fmaf(rel * rel, c1, sw));
                    ws += w;
                    bs = fmaf(w, b6[p + k], bs);
                    ds = fmaf(w, d6[p + k], ds);
                }
                const float r = f_rcp(ws);
                bx[p] = rowv ? bs * r : 0.f;   // keep NaN out for pad rows
                dx[p] = rowv ? ds * r : 0.f;
            }
            rz[rr]  = make_float2(z6[2], z6[3]);   // 0 for pad rows
            rbx[rr] = make_float2(bx[0], bx[1]);
            rdx[rr] = make_float2(dx[0], dx[1]);

            // ---- vertical blur + blend, output image row y0 + m - 4
            if (m >= 4 && m < HSTRIP + 4) {
                const int sc = (rr + 3) % 5;       // center slot (stream row m-2)
                const int ooff = base + (y0 + m - 4) * WDIM + col0;
                const float2 bCe = __ldg((const float2*)(bright + ooff));
                const float2 dCe = __ldg((const float2*)(dark   + ooff));
                float res[PX];
                #pragma unroll
                for (int p = 0; p < PX; p++) {
                    const float izc = f_rcp(p ? rz[sc].y : rz[sc].x);
                    float vws = 1.f;
                    float vbs = p ? rbx[sc].y : rbx[sc].x;
                    float vds = p ? rdx[sc].y : rdx[sc].x;
                    #pragma unroll
                    for (int j = 0; j < 5; j++) {
                        if (j == 2) continue;
                        const int sj = (rr + 1 + j) % 5;   // tap stream row m-4+j
                        const float sw = (j == 0 || j == 4) ? q4 : q1;
                        const float zj = p ? rz[sj].y : rz[sj].x;
                        float rel = fminf(fabsf(fmaf(zj, izc, -1.f)), 1.f);
                        float w = f_ex2(fmaf(rel * rel, c1, sw));
                        vws += w;
                        vbs = fmaf(w, p ? rbx[sj].y : rbx[sj].x, vbs);
                        vds = fmaf(w, p ? rdx[sj].y : rdx[sj].x, vds);
                    }
                    const float vr = f_rcp(vws);
                    const float bm = vbs * vr, dm = vds * vr;
                    const float b = p ? bCe.y : bCe.x;
                    const float d = p ? dCe.y : dCe.x;

                    // custom_pow(a, de) = exp2(de * log2(max(a, 1e-8)))
                    float devb = f_ex2(de * f_lg2(fmaxf(fabsf(b - bm), 1e-8f))) * ce;
                    float devd = fmaxf(f_ex2(de * f_lg2(fmaxf(fabsf(d - dm), 1e-8f))), eps);
                    float s = f_rcp(devb + devd);
                    res[p] = (devd * b + devb * d) * s;
                }
                *reinterpret_cast<float2*>(out + ooff) = make_float2(res[0], res[1]);
            }
        }
    }
}

extern "C" void kernel_launch(void* const* d_in, const int* in_sizes, int n_in,
                              void* d_out, int out_size)
{
    const float* bright = (const float*)d_in[0];
    const float* dark   = (const float*)d_in[1];
    const float* depths = (const float*)d_in[2];
    const float* dv     = (const float*)d_in[3];
    const float* sv     = (const float*)d_in[4];
    const float* de     = (const float*)d_in[5];
    const float* eps    = (const float*)d_in[6];
    const float* ce     = (const float*)d_in[7];
    float* out = (float*)d_out;

    dim3 grid(WDIM / TILEW, YBLOCKS, BATCH);   // 4 x 23 x 8 = 736 blocks = 1 wave
    bilat_px2p_kernel<<<grid, NT>>>(bright, dark, depths, dv, sv, de, eps, ce, out);
}

// round 14
// speedup vs baseline: 1.5366x; 1.0433x over previous
#include <cuda_runtime.h>

// BilateralBlur: barrier-free streaming separable depth-guided blur, 2 px/thread.
// B=8, H=1024, W=1024, R=2 (K=5). Block = 128 threads x 2 px = 256 columns.
// R13 decomposition (736 blocks = 1 wave at occ 5, HSTRIP=46, 10 full chunks).
// ONLY change vs R13: blend uses the ratio form (1 ex2 instead of 2).

#define HDIM 1024
#define WDIM 1024
#define BATCH 8
#define NT 128
#define PX 2
#define TILEW (NT * PX)     // 256
#define HSTRIP 46
#define YBLOCKS 23          // covers 1024 rows (last strip clamped, overlap rewrites same values)
#define NCHUNK 10           // 50 stream rows, emissions at m=4..49

__device__ __forceinline__ float f_ex2(float x){ float y; asm("ex2.approx.ftz.f32 %0, %1;" : "=f"(y) : "f"(x)); return y; }
__device__ __forceinline__ float f_lg2(float x){ float y; asm("lg2.approx.ftz.f32 %0, %1;" : "=f"(y) : "f"(x)); return y; }
__device__ __forceinline__ float f_rcp(float x){ float y; asm("rcp.approx.ftz.f32 %0, %1;" : "=f"(y) : "f"(x)); return y; }

__global__ __launch_bounds__(NT, 5)
void bilat_px2r_kernel(const float* __restrict__ bright,
                       const float* __restrict__ dark,
                       const float* __restrict__ depths,
                       const float* __restrict__ s_dv,
                       const float* __restrict__ s_sv,
                       const float* __restrict__ s_de,
                       const float* __restrict__ s_eps,
                       const float* __restrict__ s_ce,
                       float* __restrict__ out)
{
    const float L2E = 1.4426950408889634f;
    const float dv  = __ldg(s_dv);
    const float sv  = __ldg(s_sv);
    const float de  = __ldg(s_de);
    const float eps = __ldg(s_eps);
    const float ce  = __ldg(s_ce);
    const float c1  = -L2E / (2.0f * dv);   // depth-weight exponent coeff (log2)
    const float q1  = -L2E / (2.0f * sv);   // spatial log2-weight, |offset|=1
    const float q4  = 4.0f * q1;            // |offset|=2
    const float lgeps = f_lg2(eps);         // eps > 0

    const int tid  = threadIdx.x;
    const int col0 = blockIdx.x * TILEW + tid * PX;  // even, always valid
    int y0 = blockIdx.y * HSTRIP;
    if (y0 > HDIM - HSTRIP) y0 = HDIM - HSTRIP;      // bottom strip overlaps (same values)
    const int base = blockIdx.z * (HDIM * WDIM);

    const bool lv = (col0 != 0);             // left halo (cols col0-2,col0-1) valid
    const bool rv = (col0 + PX < WDIM);      // right halo (cols col0+2,col0+3) valid
    const int offL = lv ? -2 : 0;            // clamped float offsets if OOB
    const int offR = rv ?  2 : 0;

    float2 rz[5], rbx[5], rdx[5];            // stream row m -> slot m%5

    #pragma unroll 1
    for (int c = 0; c < NCHUNK; c++) {
        #pragma unroll
        for (int rr = 0; rr < 5; rr++) {
            const int m  = c * 5 + rr;
            const int gy = y0 - 2 + m;
            const bool rowv = ((unsigned)gy) < (unsigned)HDIM;
            const int gyc = rowv ? gy : (gy < 0 ? 0 : HDIM - 1);
            const int ro  = base + gyc * WDIM + col0;

            const float* pz = depths + ro;
            const float* pb = bright + ro;
            const float* pd = dark   + ro;
            const float2 zL = __ldg((const float2*)(pz + offL));
            const float2 zC = __ldg((const float2*)pz);
            const float2 zR = __ldg((const float2*)(pz + offR));
            const float2 bL = __ldg((const float2*)(pb + offL));
            const float2 bC = __ldg((const float2*)pb);
            const float2 bR = __ldg((const float2*)(pb + offR));
            const float2 dL = __ldg((const float2*)(pd + offL));
            const float2 dC = __ldg((const float2*)pd);
            const float2 dR = __ldg((const float2*)(pd + offR));

            // invalid tap => z forced to 0 => rel=1 => weight underflows to exactly 0
            const bool lm = rowv & lv;
            const bool rm = rowv & rv;
            float z6[6], b6[6], d6[6];
            z6[0] = lm   ? zL.x : 0.f;  z6[1] = lm   ? zL.y : 0.f;
            z6[2] = rowv ? zC.x : 0.f;  z6[3] = rowv ? zC.y : 0.f;
            z6[4] = rm   ? zR.x : 0.f;  z6[5] = rm   ? zR.y : 0.f;
            b6[0] = bL.x; b6[1] = bL.y; b6[2] = bC.x; b6[3] = bC.y; b6[4] = bR.x; b6[5] = bR.y;
            d6[0] = dL.x; d6[1] = dL.y; d6[2] = dC.x; d6[3] = dC.y; d6[4] = dR.x; d6[5] = dR.y;

            // ---- horizontal blur (center tap weight = 1, skipped)
            float bx[PX], dx[PX];
            #pragma unroll
            for (int p = 0; p < PX; p++) {
                const float iz = f_rcp(z6[2 + p]);
                float ws = 1.f, bs = b6[2 + p], ds = d6[2 + p];
                #pragma unroll
                for (int k = 0; k < 5; k++) {
                    if (k == 2) continue;
                    const float sw = (k == 0 || k == 4) ? q4 : q1;
                    float rel = fminf(fabsf(fmaf(z6[p + k], iz, -1.f)), 1.f);
                    float w = f_ex2(fmaf(rel * rel, c1, sw));
                    ws += w;
                    bs = fmaf(w, b6[p + k], bs);
                    ds = fmaf(w, d6[p + k], ds);
                }
                const float r = f_rcp(ws);
                bx[p] = rowv ? bs * r : 0.f;   // keep NaN out for pad rows
                dx[p] = rowv ? ds * r : 0.f;
            }
            rz[rr]  = make_float2(z6[2], z6[3]);   // 0 for pad rows
            rbx[rr] = make_float2(bx[0], bx[1]);
            rdx[rr] = make_float2(dx[0], dx[1]);

            // ---- vertical blur + blend, output image row y0 + m - 4
            if (m >= 4 && m < HSTRIP + 4) {
                const int sc = (rr + 3) % 5;       // center slot (stream row m-2)
                const int ooff = base + (y0 + m - 4) * WDIM + col0;
                const float2 bCe = __ldg((const float2*)(bright + ooff));
                const float2 dCe = __ldg((const float2*)(dark   + ooff));
                float res[PX];
                #pragma unroll
                for (int p = 0; p < PX; p++) {
                    const float izc = f_rcp(p ? rz[sc].y : rz[sc].x);
                    float vws = 1.f;
                    float vbs = p ? rbx[sc].y : rbx[sc].x;
                    float vds = p ? rdx[sc].y : rdx[sc].x;
                    #pragma unroll
                    for (int j = 0; j < 5; j++) {
                        if (j == 2) continue;
                        const int sj = (rr + 1 + j) % 5;   // tap stream row m-4+j
                        const float sw = (j == 0 || j == 4) ? q4 : q1;
                        const float zj = p ? rz[sj].y : rz[sj].x;
                        float rel = fminf(fabsf(fmaf(zj, izc, -1.f)), 1.f);
                        float w = f_ex2(fmaf(rel * rel, c1, sw));
                        vws += w;
                        vbs = fmaf(w, p ? rbx[sj].y : rbx[sj].x, vbs);
                        vds = fmaf(w, p ? rdx[sj].y : rdx[sj].x, vds);
                    }
                    const float vr = f_rcp(vws);
                    const float bm = vbs * vr, dm = vds * vr;
                    const float b = p ? bCe.y : bCe.x;
                    const float d = p ? dCe.y : dCe.x;

                    // ratio blend: t = devb/devd, devd = max(pow,eps) folded via
                    // ex2 monotonicity; out = (b + t*d) / (1 + t)
                    const float lb  = f_lg2(fmaxf(fabsf(b - bm), 1e-8f));
                    const float ld  = f_lg2(fmaxf(fabsf(d - dm), 1e-8f));
                    const float ld2 = fmaxf(de * ld, lgeps);
                    const float t   = ce * f_ex2(fmaf(de, lb, -ld2));
                    const float s   = f_rcp(1.f + t);
                    res[p] = fmaf(t, d, b) * s;
                }
                *reinterpret_cast<float2*>(out + ooff) = make_float2(res[0], res[1]);
            }
        }
    }
}

extern "C" void kernel_launch(void* const* d_in, const int* in_sizes, int n_in,
                              void* d_out, int out_size)
{
    const float* bright = (const float*)d_in[0];
    const float* dark   = (const float*)d_in[1];
    const float* depths = (const float*)d_in[2];
    const float* dv     = (const float*)d_in[3];
    const float* sv     = (const float*)d_in[4];
    const float* de     = (const float*)d_in[5];
    const float* eps    = (const float*)d_in[6];
    const float* ce     = (const float*)d_in[7];
    float* out = (float*)d_out;

    dim3 grid(WDIM / TILEW, YBLOCKS, BATCH);   // 4 x 23 x 8 = 736 blocks = 1 wave
    bilat_px2r_kernel<<<grid, NT>>>(bright, dark, depths, dv, sv, de, eps, ce, out);
}